// round 4
// baseline (speedup 1.0000x reference)
#include <cuda_runtime.h>
#include <cuda_bf16.h>
#include <math.h>

// BidirectionalALiBi: out[h, i, j] = |j - i| * m
//   m = alpha[h] if (i==0 || j==0), gamma[h] if j>i, beta[h] if j<i.
//
// Persistent grid-stride version: single wave of 1184 blocks x 256 threads.
// Flat float4 chunk index -> (h, i, j0); consecutive lanes hit consecutive
// 16B chunks (perfect STG.128 coalescing). Coefficients per chunk:
//   c1 = (i==0) ? a : ((j0 >= i) ? g : -b);   c0 = -fi * c1
//   v(j) = fma(fj, c1, c0)        (diagonal j==i yields exactly 0)
// Straddle chunks (i in (j0, j0+3)) and the j==0 edge column get fix-ups.

__global__ void __launch_bounds__(256, 8)
alibi_kernel(const float* __restrict__ alpha,
             const float* __restrict__ beta,
             const float* __restrict__ gamma,
             float4* __restrict__ out4,
             unsigned int nchunks,   // total float4 chunks = H*S*S/4
             int log2cpr,            // log2(S/4)  chunks per row
             int log2S)
{
    const unsigned int stride = gridDim.x * blockDim.x;
    const int Smask = (1 << log2S) - 1;
    const int cprmask = (1 << log2cpr) - 1;

#pragma unroll 4
    for (unsigned int idx = blockIdx.x * blockDim.x + threadIdx.x;
         idx < nchunks; idx += stride)
    {
        const int row = idx >> log2cpr;          // h*S + i
        const int j0  = (idx & cprmask) << 2;
        const int h   = row >> log2S;
        const int i   = row & Smask;

        const float a = __ldg(&alpha[h]);
        const float b = __ldg(&beta[h]);
        const float g = __ldg(&gamma[h]);

        const float fi = (float)i;
        const float fj = (float)j0;

        float c1 = (j0 >= i) ? g : -b;
        if (i == 0) c1 = a;
        const float c0 = -fi * c1;

        float4 r;
        if (i > j0 && i < j0 + 3) {
            // straddles the diagonal (rare: <0.1% of chunks)
            float* rp = reinterpret_cast<float*>(&r);
#pragma unroll
            for (int k = 0; k < 4; ++k) {
                const int j = j0 + k;
                const float m = (j > i) ? g : b;
                rp[k] = fabsf((float)j - fi) * m;
            }
        } else {
            r.x = fmaf(fj,        c1, c0);
            r.y = fmaf(fj + 1.0f, c1, c0);
            r.z = fmaf(fj + 2.0f, c1, c0);
            r.w = fmaf(fj + 3.0f, c1, c0);
        }

        if (j0 == 0 && i != 0) r.x = fi * a;     // edge column j==0

        out4[idx] = r;
    }
}

extern "C" void kernel_launch(void* const* d_in, const int* in_sizes, int n_in,
                              void* d_out, int out_size)
{
    const float* alpha = (const float*)d_in[0];
    const float* beta  = (const float*)d_in[1];
    const float* gamma = (const float*)d_in[2];
    float4* out4 = (float4*)d_out;

    const int H = in_sizes[0];                 // 16
    long long ss = (long long)out_size / H;    // S*S
    int S = (int)(sqrt((double)ss) + 0.5);

    int log2S = 0;
    while ((1 << log2S) < S) ++log2S;          // S is a power of two (2048)
    const int log2cpr = log2S - 2;             // chunks (float4) per row

    const unsigned int nchunks = (unsigned int)((long long)out_size / 4);

    const int threads = 256;
    const int blocks = 148 * 8;                // one full wave, persistent

    alibi_kernel<<<blocks, threads>>>(alpha, beta, gamma, out4,
                                      nchunks, log2cpr, log2S);
}

// round 7
// speedup vs baseline: 1.6312x; 1.6312x over previous
#include <cuda_runtime.h>
#include <cuda_bf16.h>
#include <math.h>

// BidirectionalALiBi: out[h, i, j] = |j - i| * m
//   m = alpha[h] if (i==0 || j==0), gamma[h] if j>i, beta[h] if j<i.
//
// Linear-in-j form (i != 0):
//   upper (j >= i): v = fma(j,  g, -i*g)
//   lower (j <= i): v = fma(j, -b,  i*b)
//   row i==0:       v = j * a
//   col j==0, i>0:  v = i * a
//
// R3 structure (best: one block per row, 256 threads, two coalesced float4
// chunks per thread at stride S/2) + streaming stores (__stcs, evict-first):
// write-once output should not hold L2 at normal priority.

__device__ __forceinline__ float4
chunk_val(int i, float fi, int j0, float a, float b, float g)
{
    float4 r;
    const float fj = (float)j0;
    if (i == 0) {
        r.x = fj * a;
        r.y = (fj + 1.0f) * a;
        r.z = (fj + 2.0f) * a;
        r.w = (fj + 3.0f) * a;
        return r;
    }
    if (j0 >= i) {                       // entirely upper (diag -> 0)
        const float c0 = -fi * g;
        r.x = fmaf(fj,        g, c0);
        r.y = fmaf(fj + 1.0f, g, c0);
        r.z = fmaf(fj + 2.0f, g, c0);
        r.w = fmaf(fj + 3.0f, g, c0);
    } else if (j0 + 3 <= i) {            // entirely lower (diag -> 0)
        const float c0 = fi * b;
        const float nb = -b;
        r.x = fmaf(fj,        nb, c0);
        r.y = fmaf(fj + 1.0f, nb, c0);
        r.z = fmaf(fj + 2.0f, nb, c0);
        r.w = fmaf(fj + 3.0f, nb, c0);
    } else {                             // straddles diagonal (1 thread/row)
        float* rp = reinterpret_cast<float*>(&r);
#pragma unroll
        for (int k = 0; k < 4; ++k) {
            const int j = j0 + k;
            const float m = (j > i) ? g : b;
            rp[k] = fabsf((float)j - fi) * m;
        }
    }
    if (j0 == 0) r.x = fi * a;           // edge column j==0 (i != 0 here)
    return r;
}

__global__ void __launch_bounds__(256, 8)
alibi_kernel(const float* __restrict__ alpha,
             const float* __restrict__ beta,
             const float* __restrict__ gamma,
             float* __restrict__ out,
             int S, int log2S)
{
    const int row = blockIdx.x;            // row = h * S + i
    const int h = row >> log2S;
    const int i = row - (h << log2S);

    const float a = __ldg(&alpha[h]);
    const float b = __ldg(&beta[h]);
    const float g = __ldg(&gamma[h]);
    const float fi = (float)i;

    const int half = S >> 1;               // 1024
    const int jA = threadIdx.x << 2;       // chunk 0: [0, S/2)
    const int jB = jA + half;              // chunk 1: [S/2, S)

    const float4 vA = chunk_val(i, fi, jA, a, b, g);
    const float4 vB = chunk_val(i, fi, jB, a, b, g);

    float4* __restrict__ orow =
        reinterpret_cast<float4*>(out + (size_t)row * (size_t)S);

    __stcs(orow + (jA >> 2), vA);          // STG.E.128.CS (evict-first)
    __stcs(orow + (jB >> 2), vB);
}

extern "C" void kernel_launch(void* const* d_in, const int* in_sizes, int n_in,
                              void* d_out, int out_size)
{
    const float* alpha = (const float*)d_in[0];
    const float* beta  = (const float*)d_in[1];
    const float* gamma = (const float*)d_in[2];
    float* out = (float*)d_out;

    const int H = in_sizes[0];                 // 16
    long long ss = (long long)out_size / H;    // S*S
    int S = (int)(sqrt((double)ss) + 0.5);

    int log2S = 0;
    while ((1 << log2S) < S) ++log2S;          // S is a power of two (2048)

    const int threads = 256;
    const int blocks = H * S;                  // one block per row

    alibi_kernel<<<blocks, threads>>>(alpha, beta, gamma, out, S, log2S);
}